// round 14
// baseline (speedup 1.0000x reference)
#include <cuda_runtime.h>
#include <stdint.h>

#define VOCAB 50257
#define SEQ   512
#define BATCH 8
#define KD    4      // NUM_DRAFTS
#define LD    8      // DRAFT_LEN
#define NROWS 256    // KD*LD*BATCH
#define LOGITS_ELEMS (BATCH * SEQ * VOCAB)
#define GX    4      // sampler blocks per row; stride = GX*256 = 1024
#define STRIDE 1024
#define TOTALB (NROWS * GX)        // 1024

// Per-(row,gx) outputs, plain store each launch (no reset needed)
__device__ unsigned long long g_part[NROWS * GX];
__device__ float g_sums[NROWS * GX];     // partial exp-sums (distributed over kl blocks)
__device__ unsigned int g_done;          // self-resetting completion counter

// ---- JAX partitionable threefry bits for flat index i (< 2^32):
//      (o0, o1) = threefry2x32(key=(0,42), x0=0, x1=i);  bits = o0 ^ o1
__device__ __forceinline__ uint32_t tf_bits(uint32_t i) {
    const uint32_t ks1 = 42u;
    const uint32_t ks2 = 42u ^ 0x1BD11BDAu;
    uint32_t x1 = i + ks1;
    uint32_t x0 = x1;                       // round 1 folded (x0 was 0)
    x1 = __funnelshift_l(x1, x1, 13) ^ x0;
#define TF_R(r) { x0 += x1; x1 = __funnelshift_l(x1, x1, (r)) ^ x0; }
    TF_R(15) TF_R(26) TF_R(6)
    x0 += ks1; x1 += ks2 + 1u;
    TF_R(17) TF_R(29) TF_R(16) TF_R(24)
    x0 += ks2; x1 += 2u;
    TF_R(13) TF_R(15) TF_R(26) TF_R(6)
    x1 += ks1 + 3u;
    TF_R(17) TF_R(29) TF_R(16) TF_R(24)
    x0 += ks1; x1 += ks2 + 4u;
    TF_R(13) TF_R(15) TF_R(26) TF_R(6)
    x0 += ks2; x1 += 5u;
#undef TF_R
    return x0 ^ x1;
}

// Order-preserving float -> uint32 map (total order matching IEEE < on reals)
__device__ __forceinline__ uint32_t fmap(float v) {
    uint32_t u = __float_as_uint(v);
    return (u & 0x80000000u) ? ~u : (u | 0x80000000u);
}

// -------- gumbel-argmax (screened) + distributed exp-sum + inline finalize -----
__global__ void __launch_bounds__(256, 7)
sample_kernel(const float* __restrict__ logits, float* __restrict__ out) {
    int r = blockIdx.y;          // sampling row (k,l,b) flat; b = r & 7
    int gx = blockIdx.x;
    int b = r & 7;
    int kl = r >> 3;             // 0..31: which element-of-thread this block sums
    const float* __restrict__ row = logits + ((size_t)b * SEQ + (SEQ - 1)) * VOCAB;

    __shared__ float red[256];
    __shared__ unsigned long long sbest;
    __shared__ int s_last;
    volatile __shared__ float s_thrf;    // best exactly-achieved val in this block
    volatile __shared__ float s_thrC;    // s_thrf - C0 (pre-biased screen threshold)
    if (threadIdx.x == 0) { sbest = 0ull; s_thrf = -INFINITY; s_thrC = -INFINITY; }
    __syncthreads();

    const float tiny = 1.17549435e-38f;
    const float C0 = 6.9325f;              // > 10*ln2 (sup gumbel below BITS_HI) + margin
    const uint32_t BITS_HI = 0xFFC00000u;  // bits >= this  <=>  mantissa >= 2^23-2^13
    unsigned long long best = 0ull;
    uint32_t base = (uint32_t)r * (uint32_t)VOCAB;
    int v0 = (gx << 8) + threadIdx.x;      // 0..1023
    uint32_t ctr = base + (uint32_t)v0;
    const float* p = row + v0;

    // exp-sum assignment: this block sums per-thread elements g == kl (and
    // g == kl+32 when kl <= 15); kl == 16 also owns the 49th element (g=48).
    int lane4 = kl & 3, grp1 = kl >> 2;    // element g=kl lives in group grp1, slot lane4
    int grp2 = (kl <= 15) ? (grp1 + 8) : -1;
    float s = 0.0f;

    #define EXACT_EVAL(bitsX, lgtX, vX)                                           \
        {                                                                         \
            uint32_t mm = (bitsX) >> 9;                                           \
            float f = __uint_as_float(mm | 0x3f800000u) - 1.0f;                   \
            float u = fmaxf(tiny, f + tiny);                                      \
            float val = (lgtX) - logf(-logf(u));                                  \
            unsigned long long pk =                                               \
                ((unsigned long long)fmap(val) << 32) |                           \
                (unsigned long long)(0xFFFFFFFFu - (uint32_t)(vX));               \
            if (pk > best) best = pk;                                             \
            if (val > s_thrf) { s_thrf = val; s_thrC = val - C0; }                \
        }

    // 12 groups of 4 + 1 single = 49 strided elements, all in-range:
    // v0 + 48*1024 <= 1023 + 49152 = 50175 < VOCAB.
    #pragma unroll 1
    for (int g = 0; g < 12; ++g) {
        float thrC = s_thrC;               // one volatile LDS per group
        uint32_t b0 = tf_bits(ctr);
        uint32_t b1 = tf_bits(ctr + STRIDE);
        uint32_t b2 = tf_bits(ctr + 2 * STRIDE);
        uint32_t b3 = tf_bits(ctr + 3 * STRIDE);
        float l0 = p[0], l1 = p[STRIDE], l2 = p[2 * STRIDE], l3 = p[3 * STRIDE];
        if (b0 >= BITS_HI || l0 >= thrC) EXACT_EVAL(b0, l0, ctr - base);
        if (b1 >= BITS_HI || l1 >= thrC) EXACT_EVAL(b1, l1, ctr + STRIDE - base);
        if (b2 >= BITS_HI || l2 >= thrC) EXACT_EVAL(b2, l2, ctr + 2 * STRIDE - base);
        if (b3 >= BITS_HI || l3 >= thrC) EXACT_EVAL(b3, l3, ctr + 3 * STRIDE - base);
        if (g == grp1 || g == grp2) {      // rare (1-2 of 12): exp-sum contribution
            float lv = (lane4 == 0) ? l0 : (lane4 == 1) ? l1 : (lane4 == 2) ? l2 : l3;
            s += expf(lv);
        }
        ctr += 4 * STRIDE; p += 4 * STRIDE;
    }
    {   // 49th element (g = 48)
        float thrC = s_thrC;
        uint32_t bx = tf_bits(ctr);
        float lx = p[0];
        if (bx >= BITS_HI || lx >= thrC) EXACT_EVAL(bx, lx, ctr - base);
        if (kl == 16) s += expf(lx);
    }
    // remainder elements 50176..50256 (81): argmax by gx==0 of every row;
    // exp-sum once per b by the (kl==0, gx==0) block.
    if (gx == 0 && threadIdx.x < 81) {
        uint32_t vr = 50176u + (uint32_t)threadIdx.x;
        uint32_t bx = tf_bits(base + vr);
        float lx = row[vr];
        float thrC = s_thrC;
        if (bx >= BITS_HI || lx >= thrC) EXACT_EVAL(bx, lx, vr);
        if (kl == 0) s += expf(lx);
    }
    #undef EXACT_EVAL

    atomicMax(&sbest, best);
    red[threadIdx.x] = s;
    __syncthreads();
    for (int st = 128; st > 0; st >>= 1) {            // deterministic tree reduce
        if (threadIdx.x < st) red[threadIdx.x] += red[threadIdx.x + st];
        __syncthreads();
    }
    if (threadIdx.x == 0) {
        g_part[r * GX + gx] = sbest;
        g_sums[r * GX + gx] = red[0];
    }

    // ---------------- completion: last block runs the finalize --------------------
    __threadfence();
    if (threadIdx.x == 0) {
        unsigned int d = atomicAdd(&g_done, 1u);
        s_last = (d == TOTALB - 1);
    }
    __syncthreads();
    if (!s_last) return;
    if (threadIdx.x == 0) g_done = 0;    // replay-safe reset
    __threadfence();

    __shared__ float probs_s[NROWS];
    __shared__ float meanp_s[BATCH * KD];
    __shared__ float ssum_s[BATCH];
    int o = threadIdx.x;                 // output layout (b, k, l)
    int ob = o >> 5, ok = (o >> 3) & 3, ol = o & 7;
    int rowidx = ok * 64 + ol * 8 + ob;  // gumbel-field row (k, l, b)
    int w = o >> 5, lane = o & 31;

    // warp w reduces the 128 exp-sum partials of batch row w (fixed order)
    {
        int rr = w + 8 * lane;           // rows of batch w, kl = lane
        float sw = 0.0f;
        #pragma unroll
        for (int i = 0; i < GX; i++) sw += g_sums[rr * GX + i];
        #pragma unroll
        for (int sh = 16; sh > 0; sh >>= 1)
            sw += __shfl_down_sync(0xFFFFFFFFu, sw, sh);
        if (lane == 0) ssum_s[w] = sw;
    }

    unsigned long long pk = g_part[rowidx * GX];
    #pragma unroll
    for (int i = 1; i < GX; i++) {
        unsigned long long q = g_part[rowidx * GX + i];
        if (q > pk) pk = q;
    }
    __syncthreads();

    uint32_t tok = 0xFFFFFFFFu - (uint32_t)(pk & 0xFFFFFFFFull);
    float lg = logits[((size_t)ob * SEQ + (SEQ - 1)) * VOCAB + tok];
    float prob = expf(lg) / ssum_s[ob];  // no-max softmax (unit-normal logits: safe)

    out[o] = (float)tok;                               // draft_tokens
    out[NROWS + o] = prob;                             // draft_probs
    out[2 * NROWS + o] = (prob >= 0.8f) ? 1.0f : 0.0f; // accepted_mask
    probs_s[o] = prob;
    __syncthreads();

    if (o < BATCH * KD) {                              // (b, k)
        int bb = o >> 2, kk = o & 3;
        float sp = 0.0f, sm = 0.0f;
        #pragma unroll
        for (int ll = 0; ll < LD; ll++) {
            float pv = probs_s[bb * 32 + kk * 8 + ll];
            sp += pv;
            sm += (pv >= 0.8f) ? 1.0f : 0.0f;
        }
        out[3 * NROWS + o] = sm / 8.0f;                // acceptance_ratio
        meanp_s[o] = sp / 8.0f;
    }
    __syncthreads();

    if (o < BATCH) {                                   // best_draft_idx (first max)
        int bestk = 0;
        float bv = meanp_s[o * 4];
        #pragma unroll
        for (int kk = 1; kk < KD; kk++) {
            float v2 = meanp_s[o * 4 + kk];
            if (v2 > bv) { bv = v2; bestk = kk; }
        }
        out[3 * NROWS + 32 + o] = (float)bestk;
    }
}

extern "C" void kernel_launch(void* const* d_in, const int* in_sizes, int n_in,
                              void* d_out, int out_size) {
    int li = 1;
    for (int i = 0; i < n_in; i++) {
        if (in_sizes[i] == LOGITS_ELEMS) { li = i; break; }
    }
    const float* logits = (const float*)d_in[li];
    float* out = (float*)d_out;

    dim3 gridB(GX, NROWS);
    sample_kernel<<<gridB, 256>>>(logits, out);
}